// round 10
// baseline (speedup 1.0000x reference)
#include <cuda_runtime.h>
#include <cuda_fp16.h>
#include <math.h>

// NodeConv:
//   xs = [x | gs]  (133)
//   y_neg[n]  = xs[n] @ W_neg[0:133] + b_neg           (per NODE, stored fp16)
//   out[n]    = elu(xs[n] @ W_root + b_root)
//   out[dst] += sum_{e: dst(e)=dst} elu(y_neg[src(e)] + ea[e] @ W_neg[133:139])
//
// CSR build + per-node warp gather (R9 winner, unchanged).
// Node GEMM moved to mma.sync.m16n8k8.tf32: A and W staged to smem as tf32,
// W in a fragment-permuted layout so B-frags load as LDS.128.

#define NMAX 100000
#define EMAX 1600000
#define NBMAX ((NMAX + 255) / 256)

__device__ __half g_yneg[(size_t)NMAX * 128];
__device__ int2   g_se[EMAX];                 // sorted-by-dst: {src, eid}
__device__ int    g_count[NMAX];
__device__ int    g_offset[NMAX + 1];
__device__ int    g_cursor[NMAX];
__device__ int    g_blocksum[NBMAX];
__device__ int    g_blockoff[NBMAX];
__device__ int    g_is64;

// Branchless ELU: exact for v>=0 (__expf(0)==1), ~1e-7 abs err for v<0.
__device__ __forceinline__ float eluf(float v) {
    float neg = fminf(v, 0.0f);
    float pos = fmaxf(v, 0.0f);
    return pos + (__expf(neg) - 1.0f);
}

__device__ __forceinline__ int load_idx(const void* ei, int is64, size_t pos) {
    return is64 ? (int)__ldg((const long long*)ei + pos)
                : __ldg((const int*)ei + pos);
}

// ---------------------------------------------------------------------------
__global__ void prep_kernel(const int* __restrict__ ei32, int nwords, int N) {
    if (blockIdx.x == 0) {
        int nz = 0;
        for (int i = 1 + 2 * threadIdx.x; i < min(nwords, 4096); i += 2 * blockDim.x)
            nz |= (ei32[i] != 0);
        int any = __syncthreads_or(nz);
        if (threadIdx.x == 0) g_is64 = any ? 0 : 1;
    }
    for (int i = blockIdx.x * blockDim.x + threadIdx.x; i < N;
         i += gridDim.x * blockDim.x)
        g_count[i] = 0;
}

// ---------------------------------------------------------------------------
__global__ void hist_kernel(const void* __restrict__ ei, int E) {
    const int is64 = g_is64;
    int e = blockIdx.x * blockDim.x + threadIdx.x;
    if (e < E) atomicAdd(&g_count[load_idx(ei, is64, e)], 1);
}

// ---------------------------------------------------------------------------
__global__ __launch_bounds__(256)
void scan1_kernel(int N) {
    const int tid = threadIdx.x, lane = tid & 31, w = tid >> 5;
    __shared__ int wsum[8];
    int i = blockIdx.x * 256 + tid;
    int v = (i < N) ? g_count[i] : 0;
#pragma unroll
    for (int o = 16; o > 0; o >>= 1) v += __shfl_down_sync(0xffffffffu, v, o);
    if (lane == 0) wsum[w] = v;
    __syncthreads();
    if (tid == 0) {
        int s = 0;
#pragma unroll
        for (int k = 0; k < 8; k++) s += wsum[k];
        g_blocksum[blockIdx.x] = s;
    }
}

__global__ __launch_bounds__(1024)
void scan2_kernel(int NB) {
    const int tid = threadIdx.x, lane = tid & 31, w = tid >> 5;
    __shared__ int wtot[32];
    int c = (tid < NB) ? g_blocksum[tid] : 0;
    int v = c;
#pragma unroll
    for (int o = 1; o < 32; o <<= 1) {
        int t = __shfl_up_sync(0xffffffffu, v, o);
        if (lane >= o) v += t;
    }
    if (lane == 31) wtot[w] = v;
    __syncthreads();
    if (w == 0) {
        int s = wtot[lane];
#pragma unroll
        for (int o = 1; o < 32; o <<= 1) {
            int t = __shfl_up_sync(0xffffffffu, s, o);
            if (lane >= o) s += t;
        }
        wtot[lane] = s;
    }
    __syncthreads();
    int excl = ((w == 0) ? 0 : wtot[w - 1]) + v - c;
    if (tid < NB) g_blockoff[tid] = excl;
}

__global__ __launch_bounds__(256)
void scan3_kernel(int N, int E) {
    const int tid = threadIdx.x, lane = tid & 31, w = tid >> 5;
    __shared__ int wtot[8];
    int i = blockIdx.x * 256 + tid;
    int c = (i < N) ? g_count[i] : 0;
    int v = c;
#pragma unroll
    for (int o = 1; o < 32; o <<= 1) {
        int t = __shfl_up_sync(0xffffffffu, v, o);
        if (lane >= o) v += t;
    }
    if (lane == 31) wtot[w] = v;
    __syncthreads();
    if (w == 0 && lane < 8) {
        int s = wtot[lane];
#pragma unroll
        for (int o = 1; o < 8; o <<= 1) {
            int t = __shfl_up_sync(0x000000ffu, s, o);
            if (lane >= o) s += t;
        }
        wtot[lane] = s;
    }
    __syncthreads();
    int excl = g_blockoff[blockIdx.x] + ((w == 0) ? 0 : wtot[w - 1]) + v - c;
    if (i < N) {
        g_offset[i] = excl;
        g_cursor[i] = excl;
    }
    if (i == 0) g_offset[N] = E;
}

// ---------------------------------------------------------------------------
// Scatter: write {src, eid} into dst bucket. One 8B random store per edge.
// ---------------------------------------------------------------------------
__global__ __launch_bounds__(256)
void scatter_kernel(const void* __restrict__ ei, int E) {
    const int is64 = g_is64;
    int e = blockIdx.x * blockDim.x + threadIdx.x;
    if (e >= E) return;
    int dst = load_idx(ei, is64, e);
    int src = load_idx(ei, is64, (size_t)E + e);
    int pos = atomicAdd(&g_cursor[dst], 1);
    g_se[pos] = make_int2(src, e);
}

// ---------------------------------------------------------------------------
// K1: node GEMM on mma.sync.m16n8k8.tf32.
// Tile: 64 nodes x 256 outs (128 neg | 128 root), K=133 padded to 136.
// 8 warps = 4 M-groups (16 rows) x 2 col-groups (128 cols).
// smem: As[136][68] tf32; Ws permuted [k][cg][gid][j] stride 260 (B-frags as
// LDS.128, per-phase conflict-free).
// ---------------------------------------------------------------------------
#define AS_WORDS (136 * 68)
#define WS_WORDS (136 * 260)

__global__ __launch_bounds__(256, 1)
void node_gemm_kernel(const float* __restrict__ x,
                      const float* __restrict__ gs,
                      const float* __restrict__ W_neg,   // [139][128]
                      const float* __restrict__ b_neg,
                      const float* __restrict__ W_root,  // [133][128]
                      const float* __restrict__ b_root,
                      float* __restrict__ out,
                      int N)
{
    extern __shared__ unsigned sm[];
    unsigned* As = sm;                 // [k][m] stride 68
    unsigned* Ws = sm + AS_WORDS;      // [k]*260 + cg*128 + gid*16 + j
    const int tid = threadIdx.x;
    const int n0 = blockIdx.x * 64;

    // Stage A -> tf32
    for (int i = tid; i < 64 * 136; i += 256) {
        int m = i / 136, k = i - m * 136;
        int n = n0 + m;
        float v = 0.0f;
        if (n < N && k < 133)
            v = (k < 128) ? x[(size_t)n * 128 + k] : gs[(size_t)n * 5 + (k - 128)];
        unsigned t;
        asm("cvt.rna.tf32.f32 %0, %1;" : "=r"(t) : "f"(v));
        As[k * 68 + m] = t;
    }
    // Stage W -> tf32, permuted
    for (int i = tid; i < 136 * 256; i += 256) {
        int k = i >> 8, n = i & 255;
        float v = 0.0f;
        if (k < 133)
            v = (n < 128) ? W_neg[(size_t)k * 128 + n]
                          : W_root[(size_t)k * 128 + (n - 128)];
        unsigned t;
        asm("cvt.rna.tf32.f32 %0, %1;" : "=r"(t) : "f"(v));
        int cg = n >> 7, rem = n & 127, g = rem & 7, j = rem >> 3;
        Ws[k * 260 + cg * 128 + g * 16 + j] = t;
    }
    __syncthreads();

    const int w = tid >> 5, lane = tid & 31;
    const int tig = lane & 3, gid = lane >> 2;
    const int rw = w & 3, cg = w >> 2;
    const int grow = rw * 16;
    const float* bsel = cg ? b_root : b_neg;

    float acc[16][4];
#pragma unroll
    for (int j = 0; j < 16; j++) {
        float bb0 = __ldg(bsel + 8 * j + 2 * tig);
        float bb1 = __ldg(bsel + 8 * j + 2 * tig + 1);
        acc[j][0] = bb0; acc[j][1] = bb1;
        acc[j][2] = bb0; acc[j][3] = bb1;
    }

    const unsigned* wb = Ws + cg * 128 + gid * 16;

#pragma unroll 1
    for (int s = 0; s < 17; s++) {
        const int k0 = s * 8;
        unsigned a0 = As[(k0 + tig) * 68 + grow + gid];
        unsigned a1 = As[(k0 + tig) * 68 + grow + gid + 8];
        unsigned a2 = As[(k0 + tig + 4) * 68 + grow + gid];
        unsigned a3 = As[(k0 + tig + 4) * 68 + grow + gid + 8];
        uint4 B0[4], B1[4];
#pragma unroll
        for (int q = 0; q < 4; q++) {
            B0[q] = *(const uint4*)(wb + (k0 + tig) * 260 + 4 * q);
            B1[q] = *(const uint4*)(wb + (k0 + tig + 4) * 260 + 4 * q);
        }
#pragma unroll
        for (int q = 0; q < 4; q++) {
#define MMA_T(J, BB0, BB1)                                                     \
    asm("mma.sync.aligned.m16n8k8.row.col.f32.tf32.tf32.f32 "                  \
        "{%0,%1,%2,%3},{%4,%5,%6,%7},{%8,%9},{%0,%1,%2,%3};"                   \
        : "+f"(acc[J][0]), "+f"(acc[J][1]), "+f"(acc[J][2]), "+f"(acc[J][3])   \
        : "r"(a0), "r"(a1), "r"(a2), "r"(a3), "r"(BB0), "r"(BB1))
            MMA_T(4 * q + 0, B0[q].x, B1[q].x);
            MMA_T(4 * q + 1, B0[q].y, B1[q].y);
            MMA_T(4 * q + 2, B0[q].z, B1[q].z);
            MMA_T(4 * q + 3, B0[q].w, B1[q].w);
#undef MMA_T
        }
    }

    // Epilogue: D row = grow+gid (+8), col = 8j + 2tig (+1).
    const int r0 = n0 + grow + gid;
    const int r1 = r0 + 8;
#pragma unroll
    for (int j = 0; j < 16; j++) {
        int col = 8 * j + 2 * tig;
        if (cg == 0) {
            if (r0 < N)
                *(__half2*)(g_yneg + (size_t)r0 * 128 + col) =
                    __float22half2_rn(make_float2(acc[j][0], acc[j][1]));
            if (r1 < N)
                *(__half2*)(g_yneg + (size_t)r1 * 128 + col) =
                    __float22half2_rn(make_float2(acc[j][2], acc[j][3]));
        } else {
            if (r0 < N) {
                float2 o = make_float2(eluf(acc[j][0]), eluf(acc[j][1]));
                *(float2*)(out + (size_t)r0 * 128 + col) = o;
            }
            if (r1 < N) {
                float2 o = make_float2(eluf(acc[j][2]), eluf(acc[j][3]));
                *(float2*)(out + (size_t)r1 * 128 + col) = o;
            }
        }
    }
}

// ---------------------------------------------------------------------------
// Gather (R9 winner, unchanged): one warp per node, unroll x4, fp16 y_neg.
// ---------------------------------------------------------------------------
__global__ __launch_bounds__(256)
void gather_kernel(const float* __restrict__ W_neg,      // [139][128]
                   const float* __restrict__ edge_attr,  // [E][6]
                   float* __restrict__ out, int N)
{
    const int lane = threadIdx.x & 31;
    const int warp = blockIdx.x * (blockDim.x >> 5) + (threadIdx.x >> 5);
    if (warp >= N) return;
    const int n = warp;

    float4 w2[6];
#pragma unroll
    for (int d = 0; d < 6; d++)
        w2[d] = __ldg((const float4*)(W_neg + (size_t)(133 + d) * 128) + lane);

    const int beg = __ldg(&g_offset[n]);
    const int end = __ldg(&g_offset[n + 1]);
    float4 acc = make_float4(0.f, 0.f, 0.f, 0.f);

    int j = beg;
    for (; j + 4 <= end; j += 4) {
        int2   se[4];
        uint2  hh[4];
        float2 a01[4], a23[4], a45[4];
#pragma unroll
        for (int u = 0; u < 4; u++) se[u] = __ldg(&g_se[j + u]);
#pragma unroll
        for (int u = 0; u < 4; u++)
            hh[u] = __ldg((const uint2*)(g_yneg + (size_t)se[u].x * 128) + lane);
#pragma unroll
        for (int u = 0; u < 4; u++) {
            const float2* ea = (const float2*)(edge_attr + (size_t)se[u].y * 6);
            a01[u] = __ldg(ea + 0);
            a23[u] = __ldg(ea + 1);
            a45[u] = __ldg(ea + 2);
        }
#pragma unroll
        for (int u = 0; u < 4; u++) {
            float2 f01 = __half22float2(*(__half2*)&hh[u].x);
            float2 f23 = __half22float2(*(__half2*)&hh[u].y);
            float4 v = make_float4(f01.x, f01.y, f23.x, f23.y);
            v.x += a01[u].x * w2[0].x + a01[u].y * w2[1].x + a23[u].x * w2[2].x
                 + a23[u].y * w2[3].x + a45[u].x * w2[4].x + a45[u].y * w2[5].x;
            v.y += a01[u].x * w2[0].y + a01[u].y * w2[1].y + a23[u].x * w2[2].y
                 + a23[u].y * w2[3].y + a45[u].x * w2[4].y + a45[u].y * w2[5].y;
            v.z += a01[u].x * w2[0].z + a01[u].y * w2[1].z + a23[u].x * w2[2].z
                 + a23[u].y * w2[3].z + a45[u].x * w2[4].z + a45[u].y * w2[5].z;
            v.w += a01[u].x * w2[0].w + a01[u].y * w2[1].w + a23[u].x * w2[2].w
                 + a23[u].y * w2[3].w + a45[u].x * w2[4].w + a45[u].y * w2[5].w;
            acc.x += eluf(v.x);
            acc.y += eluf(v.y);
            acc.z += eluf(v.z);
            acc.w += eluf(v.w);
        }
    }
    for (; j < end; j++) {
        int2 se = __ldg(&g_se[j]);
        uint2 hh = __ldg((const uint2*)(g_yneg + (size_t)se.x * 128) + lane);
        const float2* ea = (const float2*)(edge_attr + (size_t)se.y * 6);
        float2 a01 = __ldg(ea + 0);
        float2 a23 = __ldg(ea + 1);
        float2 a45 = __ldg(ea + 2);
        float2 f01 = __half22float2(*(__half2*)&hh.x);
        float2 f23 = __half22float2(*(__half2*)&hh.y);
        float4 v = make_float4(f01.x, f01.y, f23.x, f23.y);
        v.x += a01.x * w2[0].x + a01.y * w2[1].x + a23.x * w2[2].x
             + a23.y * w2[3].x + a45.x * w2[4].x + a45.y * w2[5].x;
        v.y += a01.x * w2[0].y + a01.y * w2[1].y + a23.x * w2[2].y
             + a23.y * w2[3].y + a45.x * w2[4].y + a45.y * w2[5].y;
        v.z += a01.x * w2[0].z + a01.y * w2[1].z + a23.x * w2[2].z
             + a23.y * w2[3].z + a45.x * w2[4].z + a45.y * w2[5].z;
        v.w += a01.x * w2[0].w + a01.y * w2[1].w + a23.x * w2[2].w
             + a23.y * w2[3].w + a45.x * w2[4].w + a45.y * w2[5].w;
        acc.x += eluf(v.x);
        acc.y += eluf(v.y);
        acc.z += eluf(v.z);
        acc.w += eluf(v.w);
    }

    float4* o = (float4*)(out + (size_t)n * 128) + lane;
    float4 cur = *o;
    cur.x += acc.x; cur.y += acc.y; cur.z += acc.z; cur.w += acc.w;
    *o = cur;
}

// ---------------------------------------------------------------------------
extern "C" void kernel_launch(void* const* d_in, const int* in_sizes, int n_in,
                              void* d_out, int out_size)
{
    const float* x      = (const float*)d_in[0];
    const void*  ei     = d_in[1];
    const float* eattr  = (const float*)d_in[2];
    const float* gs     = (const float*)d_in[3];
    const float* W_neg  = (const float*)d_in[4];
    const float* b_neg  = (const float*)d_in[5];
    const float* W_root = (const float*)d_in[6];
    const float* b_root = (const float*)d_in[7];
    float* out = (float*)d_out;

    const int N  = in_sizes[0] / 128;   // 100000
    const int E  = in_sizes[2] / 6;     // 1600000
    const int NB = (N + 255) / 256;

    prep_kernel<<<128, 256>>>((const int*)ei, in_sizes[1], N);
    hist_kernel<<<(E + 255) / 256, 256>>>(ei, E);
    scan1_kernel<<<NB, 256>>>(N);
    scan2_kernel<<<1, 1024>>>(NB);
    scan3_kernel<<<NB, 256>>>(N, E);
    scatter_kernel<<<(E + 255) / 256, 256>>>(ei, E);

    const size_t smem = (size_t)(AS_WORDS + WS_WORDS) * 4;  // 178,432 B
    cudaFuncSetAttribute(node_gemm_kernel,
                         cudaFuncAttributeMaxDynamicSharedMemorySize, (int)smem);
    node_gemm_kernel<<<(N + 63) / 64, 256, smem>>>(x, gs, W_neg, b_neg,
                                                   W_root, b_root, out, N);

    gather_kernel<<<(N * 32 + 255) / 256, 256>>>(W_neg, eattr, out, N);
}

// round 11
// speedup vs baseline: 1.5090x; 1.5090x over previous
#include <cuda_runtime.h>
#include <cuda_fp16.h>
#include <math.h>

// NodeConv:
//   xs = [x | gs]  (133)
//   y_neg[n]  = xs[n] @ W_neg[0:133] + b_neg           (per NODE, stored fp16)
//   out[n]    = elu(xs[n] @ W_root + b_root)
//   out[dst] += sum_{e: dst(e)=dst} elu(y_neg[src(e)] + ea[e] @ W_neg[133:139])
//
// R9 winner config (f32x2 GEMM + fp16 y_neg + CSR gather), with the gather
// main loop deepened to unroll-8 for more memory-level parallelism.

#define NMAX 100000
#define EMAX 1600000
#define NBMAX ((NMAX + 255) / 256)

__device__ __half g_yneg[(size_t)NMAX * 128];
__device__ int2   g_se[EMAX];                 // sorted-by-dst: {src, eid}
__device__ int    g_count[NMAX];
__device__ int    g_offset[NMAX + 1];
__device__ int    g_cursor[NMAX];
__device__ int    g_blocksum[NBMAX];
__device__ int    g_blockoff[NBMAX];
__device__ int    g_is64;

// Branchless ELU: exact for v>=0 (__expf(0)==1), ~1e-7 abs err for v<0.
__device__ __forceinline__ float eluf(float v) {
    float neg = fminf(v, 0.0f);
    float pos = fmaxf(v, 0.0f);
    return pos + (__expf(neg) - 1.0f);
}

__device__ __forceinline__ int load_idx(const void* ei, int is64, size_t pos) {
    return is64 ? (int)__ldg((const long long*)ei + pos)
                : __ldg((const int*)ei + pos);
}

// ---------------------------------------------------------------------------
__global__ void prep_kernel(const int* __restrict__ ei32, int nwords, int N) {
    if (blockIdx.x == 0) {
        int nz = 0;
        for (int i = 1 + 2 * threadIdx.x; i < min(nwords, 4096); i += 2 * blockDim.x)
            nz |= (ei32[i] != 0);
        int any = __syncthreads_or(nz);
        if (threadIdx.x == 0) g_is64 = any ? 0 : 1;
    }
    for (int i = blockIdx.x * blockDim.x + threadIdx.x; i < N;
         i += gridDim.x * blockDim.x)
        g_count[i] = 0;
}

// ---------------------------------------------------------------------------
__global__ void hist_kernel(const void* __restrict__ ei, int E) {
    const int is64 = g_is64;
    int e = blockIdx.x * blockDim.x + threadIdx.x;
    if (e < E) atomicAdd(&g_count[load_idx(ei, is64, e)], 1);
}

// ---------------------------------------------------------------------------
__global__ __launch_bounds__(256)
void scan1_kernel(int N) {
    const int tid = threadIdx.x, lane = tid & 31, w = tid >> 5;
    __shared__ int wsum[8];
    int i = blockIdx.x * 256 + tid;
    int v = (i < N) ? g_count[i] : 0;
#pragma unroll
    for (int o = 16; o > 0; o >>= 1) v += __shfl_down_sync(0xffffffffu, v, o);
    if (lane == 0) wsum[w] = v;
    __syncthreads();
    if (tid == 0) {
        int s = 0;
#pragma unroll
        for (int k = 0; k < 8; k++) s += wsum[k];
        g_blocksum[blockIdx.x] = s;
    }
}

__global__ __launch_bounds__(1024)
void scan2_kernel(int NB) {
    const int tid = threadIdx.x, lane = tid & 31, w = tid >> 5;
    __shared__ int wtot[32];
    int c = (tid < NB) ? g_blocksum[tid] : 0;
    int v = c;
#pragma unroll
    for (int o = 1; o < 32; o <<= 1) {
        int t = __shfl_up_sync(0xffffffffu, v, o);
        if (lane >= o) v += t;
    }
    if (lane == 31) wtot[w] = v;
    __syncthreads();
    if (w == 0) {
        int s = wtot[lane];
#pragma unroll
        for (int o = 1; o < 32; o <<= 1) {
            int t = __shfl_up_sync(0xffffffffu, s, o);
            if (lane >= o) s += t;
        }
        wtot[lane] = s;
    }
    __syncthreads();
    int excl = ((w == 0) ? 0 : wtot[w - 1]) + v - c;
    if (tid < NB) g_blockoff[tid] = excl;
}

__global__ __launch_bounds__(256)
void scan3_kernel(int N, int E) {
    const int tid = threadIdx.x, lane = tid & 31, w = tid >> 5;
    __shared__ int wtot[8];
    int i = blockIdx.x * 256 + tid;
    int c = (i < N) ? g_count[i] : 0;
    int v = c;
#pragma unroll
    for (int o = 1; o < 32; o <<= 1) {
        int t = __shfl_up_sync(0xffffffffu, v, o);
        if (lane >= o) v += t;
    }
    if (lane == 31) wtot[w] = v;
    __syncthreads();
    if (w == 0 && lane < 8) {
        int s = wtot[lane];
#pragma unroll
        for (int o = 1; o < 8; o <<= 1) {
            int t = __shfl_up_sync(0x000000ffu, s, o);
            if (lane >= o) s += t;
        }
        wtot[lane] = s;
    }
    __syncthreads();
    int excl = g_blockoff[blockIdx.x] + ((w == 0) ? 0 : wtot[w - 1]) + v - c;
    if (i < N) {
        g_offset[i] = excl;
        g_cursor[i] = excl;
    }
    if (i == 0) g_offset[N] = E;
}

// ---------------------------------------------------------------------------
// Scatter: write {src, eid} into dst bucket. One 8B random store per edge.
// ---------------------------------------------------------------------------
__global__ __launch_bounds__(256)
void scatter_kernel(const void* __restrict__ ei, int E) {
    const int is64 = g_is64;
    int e = blockIdx.x * blockDim.x + threadIdx.x;
    if (e >= E) return;
    int dst = load_idx(ei, is64, e);
    int src = load_idx(ei, is64, (size_t)E + e);
    int pos = atomicAdd(&g_cursor[dst], 1);
    g_se[pos] = make_int2(src, e);
}

// ---------------------------------------------------------------------------
// K1: fused node GEMM on fma.rn.f32x2 (R8/R9 winner).
// Tile = 64 nodes x 256 outputs (128 y_neg fp16 | 128 root fp32).
// ---------------------------------------------------------------------------
__global__ __launch_bounds__(256, 2)
void node_gemm_kernel(const float* __restrict__ x,
                      const float* __restrict__ gs,
                      const float* __restrict__ W_neg,   // [139][128]
                      const float* __restrict__ b_neg,
                      const float* __restrict__ W_root,  // [133][128]
                      const float* __restrict__ b_root,
                      float* __restrict__ out,
                      int N)
{
    __shared__ __align__(16) float As[133][68];   // transposed, 16B-aligned rows
    const int tid = threadIdx.x;
    const int n0 = blockIdx.x * 64;

    for (int i = tid; i < 64 * 133; i += 256) {
        int m = i / 133;
        int k = i - m * 133;
        int n = n0 + m;
        float v = 0.0f;
        if (n < N) v = (k < 128) ? x[(size_t)n * 128 + k]
                                 : gs[(size_t)n * 5 + (k - 128)];
        As[k][m] = v;
    }
    __syncthreads();

    const int c = tid & 31;
    const int r = tid >> 5;
    const bool isRoot = (c >= 16);
    const float* Wsel = isRoot ? W_root : W_neg;
    const float* bsel = isRoot ? b_root : b_neg;
    const int cb = (isRoot ? (c - 16) : c) * 8;

    unsigned long long acc[4][8];
#pragma unroll
    for (int j = 0; j < 8; j++) {
        float bv = __ldg(bsel + cb + j);
        unsigned long long bb;
        asm("mov.b64 %0, {%1, %1};" : "=l"(bb) : "f"(bv));
#pragma unroll
        for (int p = 0; p < 4; p++) acc[p][j] = bb;
    }

#pragma unroll 2
    for (int k = 0; k < 133; k++) {
        float4 b0 = __ldg((const float4*)(Wsel + (size_t)k * 128 + cb));
        float4 b1 = __ldg((const float4*)(Wsel + (size_t)k * 128 + cb + 4));
        float4 a0 = *(const float4*)&As[k][r * 8];
        float4 a1 = *(const float4*)&As[k][r * 8 + 4];

        unsigned long long ap[4], wd[8];
        asm("mov.b64 %0, {%1, %2};" : "=l"(ap[0]) : "f"(a0.x), "f"(a0.y));
        asm("mov.b64 %0, {%1, %2};" : "=l"(ap[1]) : "f"(a0.z), "f"(a0.w));
        asm("mov.b64 %0, {%1, %2};" : "=l"(ap[2]) : "f"(a1.x), "f"(a1.y));
        asm("mov.b64 %0, {%1, %2};" : "=l"(ap[3]) : "f"(a1.z), "f"(a1.w));
        asm("mov.b64 %0, {%1, %1};" : "=l"(wd[0]) : "f"(b0.x));
        asm("mov.b64 %0, {%1, %1};" : "=l"(wd[1]) : "f"(b0.y));
        asm("mov.b64 %0, {%1, %1};" : "=l"(wd[2]) : "f"(b0.z));
        asm("mov.b64 %0, {%1, %1};" : "=l"(wd[3]) : "f"(b0.w));
        asm("mov.b64 %0, {%1, %1};" : "=l"(wd[4]) : "f"(b1.x));
        asm("mov.b64 %0, {%1, %1};" : "=l"(wd[5]) : "f"(b1.y));
        asm("mov.b64 %0, {%1, %1};" : "=l"(wd[6]) : "f"(b1.z));
        asm("mov.b64 %0, {%1, %1};" : "=l"(wd[7]) : "f"(b1.w));

#pragma unroll
        for (int p = 0; p < 4; p++)
#pragma unroll
            for (int j = 0; j < 8; j++)
                asm("fma.rn.f32x2 %0, %1, %2, %0;"
                    : "+l"(acc[p][j]) : "l"(ap[p]), "l"(wd[j]));
    }

#pragma unroll
    for (int p = 0; p < 4; p++) {
        float lo[8], hi[8];
#pragma unroll
        for (int j = 0; j < 8; j++)
            asm("mov.b64 {%0, %1}, %2;" : "=f"(lo[j]), "=f"(hi[j]) : "l"(acc[p][j]));

        int n_lo = n0 + r * 8 + 2 * p;
        int n_hi = n_lo + 1;
        if (isRoot) {
            if (n_lo < N) {
                *((float4*)(out + (size_t)n_lo * 128 + cb)) =
                    make_float4(eluf(lo[0]), eluf(lo[1]), eluf(lo[2]), eluf(lo[3]));
                *((float4*)(out + (size_t)n_lo * 128 + cb + 4)) =
                    make_float4(eluf(lo[4]), eluf(lo[5]), eluf(lo[6]), eluf(lo[7]));
            }
            if (n_hi < N) {
                *((float4*)(out + (size_t)n_hi * 128 + cb)) =
                    make_float4(eluf(hi[0]), eluf(hi[1]), eluf(hi[2]), eluf(hi[3]));
                *((float4*)(out + (size_t)n_hi * 128 + cb + 4)) =
                    make_float4(eluf(hi[4]), eluf(hi[5]), eluf(hi[6]), eluf(hi[7]));
            }
        } else {
            if (n_lo < N) {
                uint4 pk;
                __half2 h0 = __float22half2_rn(make_float2(lo[0], lo[1]));
                __half2 h1 = __float22half2_rn(make_float2(lo[2], lo[3]));
                __half2 h2 = __float22half2_rn(make_float2(lo[4], lo[5]));
                __half2 h3 = __float22half2_rn(make_float2(lo[6], lo[7]));
                pk.x = *(unsigned*)&h0; pk.y = *(unsigned*)&h1;
                pk.z = *(unsigned*)&h2; pk.w = *(unsigned*)&h3;
                *((uint4*)(g_yneg + (size_t)n_lo * 128 + cb)) = pk;
            }
            if (n_hi < N) {
                uint4 pk;
                __half2 h0 = __float22half2_rn(make_float2(hi[0], hi[1]));
                __half2 h1 = __float22half2_rn(make_float2(hi[2], hi[3]));
                __half2 h2 = __float22half2_rn(make_float2(hi[4], hi[5]));
                __half2 h3 = __float22half2_rn(make_float2(hi[6], hi[7]));
                pk.x = *(unsigned*)&h0; pk.y = *(unsigned*)&h1;
                pk.z = *(unsigned*)&h2; pk.w = *(unsigned*)&h3;
                *((uint4*)(g_yneg + (size_t)n_hi * 128 + cb)) = pk;
            }
        }
    }
}

// ---------------------------------------------------------------------------
// Per-edge gather body (after all loads have been issued): W2 FMA + ELU + acc.
// ---------------------------------------------------------------------------
__device__ __forceinline__ void edge_accum(float4& acc, uint2 hh,
                                           float2 a01, float2 a23, float2 a45,
                                           const float4* w2) {
    float2 f01 = __half22float2(*(__half2*)&hh.x);
    float2 f23 = __half22float2(*(__half2*)&hh.y);
    float4 v = make_float4(f01.x, f01.y, f23.x, f23.y);
    v.x += a01.x * w2[0].x + a01.y * w2[1].x + a23.x * w2[2].x
         + a23.y * w2[3].x + a45.x * w2[4].x + a45.y * w2[5].x;
    v.y += a01.x * w2[0].y + a01.y * w2[1].y + a23.x * w2[2].y
         + a23.y * w2[3].y + a45.x * w2[4].y + a45.y * w2[5].y;
    v.z += a01.x * w2[0].z + a01.y * w2[1].z + a23.x * w2[2].z
         + a23.y * w2[3].z + a45.x * w2[4].z + a45.y * w2[5].z;
    v.w += a01.x * w2[0].w + a01.y * w2[1].w + a23.x * w2[2].w
         + a23.y * w2[3].w + a45.x * w2[4].w + a45.y * w2[5].w;
    acc.x += eluf(v.x);
    acc.y += eluf(v.y);
    acc.z += eluf(v.z);
    acc.w += eluf(v.w);
}

// ---------------------------------------------------------------------------
// Gather: one warp per node. Main loop unroll-8 (8 independent y_neg row
// loads in flight), then a 4-batch, then scalar tail. fp16 y_neg rows.
// ---------------------------------------------------------------------------
__global__ __launch_bounds__(256)
void gather_kernel(const float* __restrict__ W_neg,      // [139][128]
                   const float* __restrict__ edge_attr,  // [E][6]
                   float* __restrict__ out, int N)
{
    const int lane = threadIdx.x & 31;
    const int warp = blockIdx.x * (blockDim.x >> 5) + (threadIdx.x >> 5);
    if (warp >= N) return;
    const int n = warp;

    float4 w2[6];
#pragma unroll
    for (int d = 0; d < 6; d++)
        w2[d] = __ldg((const float4*)(W_neg + (size_t)(133 + d) * 128) + lane);

    const int beg = __ldg(&g_offset[n]);
    const int end = __ldg(&g_offset[n + 1]);
    float4 acc = make_float4(0.f, 0.f, 0.f, 0.f);

    int j = beg;
    for (; j + 8 <= end; j += 8) {
        int2   se[8];
        uint2  hh[8];
        float2 a01[8], a23[8], a45[8];
#pragma unroll
        for (int u = 0; u < 8; u++) se[u] = __ldg(&g_se[j + u]);
#pragma unroll
        for (int u = 0; u < 8; u++)
            hh[u] = __ldg((const uint2*)(g_yneg + (size_t)se[u].x * 128) + lane);
#pragma unroll
        for (int u = 0; u < 8; u++) {
            const float2* ea = (const float2*)(edge_attr + (size_t)se[u].y * 6);
            a01[u] = __ldg(ea + 0);
            a23[u] = __ldg(ea + 1);
            a45[u] = __ldg(ea + 2);
        }
#pragma unroll
        for (int u = 0; u < 8; u++)
            edge_accum(acc, hh[u], a01[u], a23[u], a45[u], w2);
    }
    if (j + 4 <= end) {
        int2   se[4];
        uint2  hh[4];
        float2 a01[4], a23[4], a45[4];
#pragma unroll
        for (int u = 0; u < 4; u++) se[u] = __ldg(&g_se[j + u]);
#pragma unroll
        for (int u = 0; u < 4; u++)
            hh[u] = __ldg((const uint2*)(g_yneg + (size_t)se[u].x * 128) + lane);
#pragma unroll
        for (int u = 0; u < 4; u++) {
            const float2* ea = (const float2*)(edge_attr + (size_t)se[u].y * 6);
            a01[u] = __ldg(ea + 0);
            a23[u] = __ldg(ea + 1);
            a45[u] = __ldg(ea + 2);
        }
#pragma unroll
        for (int u = 0; u < 4; u++)
            edge_accum(acc, hh[u], a01[u], a23[u], a45[u], w2);
        j += 4;
    }
    for (; j < end; j++) {
        int2 se = __ldg(&g_se[j]);
        uint2 hh = __ldg((const uint2*)(g_yneg + (size_t)se.x * 128) + lane);
        const float2* ea = (const float2*)(edge_attr + (size_t)se.y * 6);
        float2 a01 = __ldg(ea + 0);
        float2 a23 = __ldg(ea + 1);
        float2 a45 = __ldg(ea + 2);
        edge_accum(acc, hh, a01, a23, a45, w2);
    }

    float4* o = (float4*)(out + (size_t)n * 128) + lane;
    float4 cur = *o;
    cur.x += acc.x; cur.y += acc.y; cur.z += acc.z; cur.w += acc.w;
    *o = cur;
}

// ---------------------------------------------------------------------------
extern "C" void kernel_launch(void* const* d_in, const int* in_sizes, int n_in,
                              void* d_out, int out_size)
{
    const float* x      = (const float*)d_in[0];
    const void*  ei     = d_in[1];
    const float* eattr  = (const float*)d_in[2];
    const float* gs     = (const float*)d_in[3];
    const float* W_neg  = (const float*)d_in[4];
    const float* b_neg  = (const float*)d_in[5];
    const float* W_root = (const float*)d_in[6];
    const float* b_root = (const float*)d_in[7];
    float* out = (float*)d_out;

    const int N  = in_sizes[0] / 128;   // 100000
    const int E  = in_sizes[2] / 6;     // 1600000
    const int NB = (N + 255) / 256;

    prep_kernel<<<128, 256>>>((const int*)ei, in_sizes[1], N);
    hist_kernel<<<(E + 255) / 256, 256>>>(ei, E);
    scan1_kernel<<<NB, 256>>>(N);
    scan2_kernel<<<1, 1024>>>(NB);
    scan3_kernel<<<NB, 256>>>(N, E);
    scatter_kernel<<<(E + 255) / 256, 256>>>(ei, E);

    node_gemm_kernel<<<(N + 63) / 64, 256>>>(x, gs, W_neg, b_neg,
                                             W_root, b_root, out, N);

    gather_kernel<<<(N * 32 + 255) / 256, 256>>>(W_neg, eattr, out, N);
}

// round 13
// speedup vs baseline: 1.6325x; 1.0818x over previous
#include <cuda_runtime.h>
#include <cuda_fp16.h>
#include <math.h>

// NodeConv:
//   xs = [x | gs]  (133)
//   y_neg[n]  = xs[n] @ W_neg[0:133] + b_neg           (per NODE, stored fp16)
//   out[n]    = elu(xs[n] @ W_root + b_root)
//   out[dst] += sum_{e: dst(e)=dst} elu(y_neg[src(e)] + ea[e] @ W_neg[133:139])
//
// R11 winner + three changes:
//  (1) CSR-build chain runs on a forked stream, overlapping the node GEMM
//      (capture-legal fork/join via events).
//  (2) scatter stores byte offsets {src*256, eid*24} -> no per-edge address
//      IMADs in gather.
//  (3) gather accumulates max(v,0)+exp(min(v,0)) and subtracts degree once at
//      the end (saves 1 FADD per channel per edge).

#define NMAX 100000
#define EMAX 1600000
#define NBMAX ((NMAX + 255) / 256)

__device__ __half g_yneg[(size_t)NMAX * 128];
__device__ int2   g_se[EMAX];                 // sorted-by-dst: {src*256, eid*24}
__device__ int    g_count[NMAX];
__device__ int    g_offset[NMAX + 1];
__device__ int    g_cursor[NMAX];
__device__ int    g_blocksum[NBMAX];
__device__ int    g_blockoff[NBMAX];
__device__ int    g_is64;

// Branchless ELU: exact for v>=0 (__expf(0)==1), ~1e-7 abs err for v<0.
__device__ __forceinline__ float eluf(float v) {
    float neg = fminf(v, 0.0f);
    float pos = fmaxf(v, 0.0f);
    return pos + (__expf(neg) - 1.0f);
}

__device__ __forceinline__ int load_idx(const void* ei, int is64, size_t pos) {
    return is64 ? (int)__ldg((const long long*)ei + pos)
                : __ldg((const int*)ei + pos);
}

// ---------------------------------------------------------------------------
__global__ void prep_kernel(const int* __restrict__ ei32, int nwords, int N) {
    if (blockIdx.x == 0) {
        int nz = 0;
        for (int i = 1 + 2 * threadIdx.x; i < min(nwords, 4096); i += 2 * blockDim.x)
            nz |= (ei32[i] != 0);
        int any = __syncthreads_or(nz);
        if (threadIdx.x == 0) g_is64 = any ? 0 : 1;
    }
    for (int i = blockIdx.x * blockDim.x + threadIdx.x; i < N;
         i += gridDim.x * blockDim.x)
        g_count[i] = 0;
}

// ---------------------------------------------------------------------------
__global__ void hist_kernel(const void* __restrict__ ei, int E) {
    const int is64 = g_is64;
    int e = blockIdx.x * blockDim.x + threadIdx.x;
    if (e < E) atomicAdd(&g_count[load_idx(ei, is64, e)], 1);
}

// ---------------------------------------------------------------------------
__global__ __launch_bounds__(256)
void scan1_kernel(int N) {
    const int tid = threadIdx.x, lane = tid & 31, w = tid >> 5;
    __shared__ int wsum[8];
    int i = blockIdx.x * 256 + tid;
    int v = (i < N) ? g_count[i] : 0;
#pragma unroll
    for (int o = 16; o > 0; o >>= 1) v += __shfl_down_sync(0xffffffffu, v, o);
    if (lane == 0) wsum[w] = v;
    __syncthreads();
    if (tid == 0) {
        int s = 0;
#pragma unroll
        for (int k = 0; k < 8; k++) s += wsum[k];
        g_blocksum[blockIdx.x] = s;
    }
}

__global__ __launch_bounds__(1024)
void scan2_kernel(int NB) {
    const int tid = threadIdx.x, lane = tid & 31, w = tid >> 5;
    __shared__ int wtot[32];
    int c = (tid < NB) ? g_blocksum[tid] : 0;
    int v = c;
#pragma unroll
    for (int o = 1; o < 32; o <<= 1) {
        int t = __shfl_up_sync(0xffffffffu, v, o);
        if (lane >= o) v += t;
    }
    if (lane == 31) wtot[w] = v;
    __syncthreads();
    if (w == 0) {
        int s = wtot[lane];
#pragma unroll
        for (int o = 1; o < 32; o <<= 1) {
            int t = __shfl_up_sync(0xffffffffu, s, o);
            if (lane >= o) s += t;
        }
        wtot[lane] = s;
    }
    __syncthreads();
    int excl = ((w == 0) ? 0 : wtot[w - 1]) + v - c;
    if (tid < NB) g_blockoff[tid] = excl;
}

__global__ __launch_bounds__(256)
void scan3_kernel(int N, int E) {
    const int tid = threadIdx.x, lane = tid & 31, w = tid >> 5;
    __shared__ int wtot[8];
    int i = blockIdx.x * 256 + tid;
    int c = (i < N) ? g_count[i] : 0;
    int v = c;
#pragma unroll
    for (int o = 1; o < 32; o <<= 1) {
        int t = __shfl_up_sync(0xffffffffu, v, o);
        if (lane >= o) v += t;
    }
    if (lane == 31) wtot[w] = v;
    __syncthreads();
    if (w == 0 && lane < 8) {
        int s = wtot[lane];
#pragma unroll
        for (int o = 1; o < 8; o <<= 1) {
            int t = __shfl_up_sync(0x000000ffu, s, o);
            if (lane >= o) s += t;
        }
        wtot[lane] = s;
    }
    __syncthreads();
    int excl = g_blockoff[blockIdx.x] + ((w == 0) ? 0 : wtot[w - 1]) + v - c;
    if (i < N) {
        g_offset[i] = excl;
        g_cursor[i] = excl;
    }
    if (i == 0) g_offset[N] = E;
}

// ---------------------------------------------------------------------------
// Scatter: write {src*256, eid*24} (byte offsets) into dst bucket.
// ---------------------------------------------------------------------------
__global__ __launch_bounds__(256)
void scatter_kernel(const void* __restrict__ ei, int E) {
    const int is64 = g_is64;
    int e = blockIdx.x * blockDim.x + threadIdx.x;
    if (e >= E) return;
    int dst = load_idx(ei, is64, e);
    int src = load_idx(ei, is64, (size_t)E + e);
    int pos = atomicAdd(&g_cursor[dst], 1);
    g_se[pos] = make_int2(src * 256, e * 24);
}

// ---------------------------------------------------------------------------
// K1: fused node GEMM on fma.rn.f32x2 (R8/R9 winner, unchanged).
// Tile = 64 nodes x 256 outputs (128 y_neg fp16 | 128 root fp32).
// ---------------------------------------------------------------------------
__global__ __launch_bounds__(256, 2)
void node_gemm_kernel(const float* __restrict__ x,
                      const float* __restrict__ gs,
                      const float* __restrict__ W_neg,   // [139][128]
                      const float* __restrict__ b_neg,
                      const float* __restrict__ W_root,  // [133][128]
                      const float* __restrict__ b_root,
                      float* __restrict__ out,
                      int N)
{
    __shared__ __align__(16) float As[133][68];   // transposed, 16B-aligned rows
    const int tid = threadIdx.x;
    const int n0 = blockIdx.x * 64;

    for (int i = tid; i < 64 * 133; i += 256) {
        int m = i / 133;
        int k = i - m * 133;
        int n = n0 + m;
        float v = 0.0f;
        if (n < N) v = (k < 128) ? x[(size_t)n * 128 + k]
                                 : gs[(size_t)n * 5 + (k - 128)];
        As[k][m] = v;
    }
    __syncthreads();

    const int c = tid & 31;
    const int r = tid >> 5;
    const bool isRoot = (c >= 16);
    const float* Wsel = isRoot ? W_root : W_neg;
    const float* bsel = isRoot ? b_root : b_neg;
    const int cb = (isRoot ? (c - 16) : c) * 8;

    unsigned long long acc[4][8];
#pragma unroll
    for (int j = 0; j < 8; j++) {
        float bv = __ldg(bsel + cb + j);
        unsigned long long bb;
        asm("mov.b64 %0, {%1, %1};" : "=l"(bb) : "f"(bv));
#pragma unroll
        for (int p = 0; p < 4; p++) acc[p][j] = bb;
    }

#pragma unroll 2
    for (int k = 0; k < 133; k++) {
        float4 b0 = __ldg((const float4*)(Wsel + (size_t)k * 128 + cb));
        float4 b1 = __ldg((const float4*)(Wsel + (size_t)k * 128 + cb + 4));
        float4 a0 = *(const float4*)&As[k][r * 8];
        float4 a1 = *(const float4*)&As[k][r * 8 + 4];

        unsigned long long ap[4], wd[8];
        asm("mov.b64 %0, {%1, %2};" : "=l"(ap[0]) : "f"(a0.x), "f"(a0.y));
        asm("mov.b64 %0, {%1, %2};" : "=l"(ap[1]) : "f"(a0.z), "f"(a0.w));
        asm("mov.b64 %0, {%1, %2};" : "=l"(ap[2]) : "f"(a1.x), "f"(a1.y));
        asm("mov.b64 %0, {%1, %2};" : "=l"(ap[3]) : "f"(a1.z), "f"(a1.w));
        asm("mov.b64 %0, {%1, %1};" : "=l"(wd[0]) : "f"(b0.x));
        asm("mov.b64 %0, {%1, %1};" : "=l"(wd[1]) : "f"(b0.y));
        asm("mov.b64 %0, {%1, %1};" : "=l"(wd[2]) : "f"(b0.z));
        asm("mov.b64 %0, {%1, %1};" : "=l"(wd[3]) : "f"(b0.w));
        asm("mov.b64 %0, {%1, %1};" : "=l"(wd[4]) : "f"(b1.x));
        asm("mov.b64 %0, {%1, %1};" : "=l"(wd[5]) : "f"(b1.y));
        asm("mov.b64 %0, {%1, %1};" : "=l"(wd[6]) : "f"(b1.z));
        asm("mov.b64 %0, {%1, %1};" : "=l"(wd[7]) : "f"(b1.w));

#pragma unroll
        for (int p = 0; p < 4; p++)
#pragma unroll
            for (int j = 0; j < 8; j++)
                asm("fma.rn.f32x2 %0, %1, %2, %0;"
                    : "+l"(acc[p][j]) : "l"(ap[p]), "l"(wd[j]));
    }

#pragma unroll
    for (int p = 0; p < 4; p++) {
        float lo[8], hi[8];
#pragma unroll
        for (int j = 0; j < 8; j++)
            asm("mov.b64 {%0, %1}, %2;" : "=f"(lo[j]), "=f"(hi[j]) : "l"(acc[p][j]));

        int n_lo = n0 + r * 8 + 2 * p;
        int n_hi = n_lo + 1;
        if (isRoot) {
            if (n_lo < N) {
                *((float4*)(out + (size_t)n_lo * 128 + cb)) =
                    make_float4(eluf(lo[0]), eluf(lo[1]), eluf(lo[2]), eluf(lo[3]));
                *((float4*)(out + (size_t)n_lo * 128 + cb + 4)) =
                    make_float4(eluf(lo[4]), eluf(lo[5]), eluf(lo[6]), eluf(lo[7]));
            }
            if (n_hi < N) {
                *((float4*)(out + (size_t)n_hi * 128 + cb)) =
                    make_float4(eluf(hi[0]), eluf(hi[1]), eluf(hi[2]), eluf(hi[3]));
                *((float4*)(out + (size_t)n_hi * 128 + cb + 4)) =
                    make_float4(eluf(hi[4]), eluf(hi[5]), eluf(hi[6]), eluf(hi[7]));
            }
        } else {
            if (n_lo < N) {
                uint4 pk;
                __half2 h0 = __float22half2_rn(make_float2(lo[0], lo[1]));
                __half2 h1 = __float22half2_rn(make_float2(lo[2], lo[3]));
                __half2 h2 = __float22half2_rn(make_float2(lo[4], lo[5]));
                __half2 h3 = __float22half2_rn(make_float2(lo[6], lo[7]));
                pk.x = *(unsigned*)&h0; pk.y = *(unsigned*)&h1;
                pk.z = *(unsigned*)&h2; pk.w = *(unsigned*)&h3;
                *((uint4*)(g_yneg + (size_t)n_lo * 128 + cb)) = pk;
            }
            if (n_hi < N) {
                uint4 pk;
                __half2 h0 = __float22half2_rn(make_float2(hi[0], hi[1]));
                __half2 h1 = __float22half2_rn(make_float2(hi[2], hi[3]));
                __half2 h2 = __float22half2_rn(make_float2(hi[4], hi[5]));
                __half2 h3 = __float22half2_rn(make_float2(hi[6], hi[7]));
                pk.x = *(unsigned*)&h0; pk.y = *(unsigned*)&h1;
                pk.z = *(unsigned*)&h2; pk.w = *(unsigned*)&h3;
                *((uint4*)(g_yneg + (size_t)n_hi * 128 + cb)) = pk;
            }
        }
    }
}

// ---------------------------------------------------------------------------
// Per-edge gather body: W2 FMA, then accumulate max(v,0)+exp(min(v,0)).
// (The "-1" per channel is applied once per node as -degree.)
// ---------------------------------------------------------------------------
__device__ __forceinline__ void edge_accum(float4& acc, uint2 hh,
                                           float2 a01, float2 a23, float2 a45,
                                           const float4* w2) {
    float2 f01 = __half22float2(*(__half2*)&hh.x);
    float2 f23 = __half22float2(*(__half2*)&hh.y);
    float4 v = make_float4(f01.x, f01.y, f23.x, f23.y);
    v.x += a01.x * w2[0].x + a01.y * w2[1].x + a23.x * w2[2].x
         + a23.y * w2[3].x + a45.x * w2[4].x + a45.y * w2[5].x;
    v.y += a01.x * w2[0].y + a01.y * w2[1].y + a23.x * w2[2].y
         + a23.y * w2[3].y + a45.x * w2[4].y + a45.y * w2[5].y;
    v.z += a01.x * w2[0].z + a01.y * w2[1].z + a23.x * w2[2].z
         + a23.y * w2[3].z + a45.x * w2[4].z + a45.y * w2[5].z;
    v.w += a01.x * w2[0].w + a01.y * w2[1].w + a23.x * w2[2].w
         + a23.y * w2[3].w + a45.x * w2[4].w + a45.y * w2[5].w;
    acc.x += fmaxf(v.x, 0.0f); acc.x += __expf(fminf(v.x, 0.0f));
    acc.y += fmaxf(v.y, 0.0f); acc.y += __expf(fminf(v.y, 0.0f));
    acc.z += fmaxf(v.z, 0.0f); acc.z += __expf(fminf(v.z, 0.0f));
    acc.w += fmaxf(v.w, 0.0f); acc.w += __expf(fminf(v.w, 0.0f));
}

// ---------------------------------------------------------------------------
// Gather: one warp per node, unroll 8/4/1. Records hold byte offsets.
// ---------------------------------------------------------------------------
__global__ __launch_bounds__(256)
void gather_kernel(const float* __restrict__ W_neg,      // [139][128]
                   const float* __restrict__ edge_attr,  // [E][6]
                   float* __restrict__ out, int N)
{
    const int lane = threadIdx.x & 31;
    const int warp = blockIdx.x * (blockDim.x >> 5) + (threadIdx.x >> 5);
    if (warp >= N) return;
    const int n = warp;

    float4 w2[6];
#pragma unroll
    for (int d = 0; d < 6; d++)
        w2[d] = __ldg((const float4*)(W_neg + (size_t)(133 + d) * 128) + lane);

    const char* ybase  = (const char*)g_yneg + lane * 8;
    const char* eabase = (const char*)edge_attr;

    const int beg = __ldg(&g_offset[n]);
    const int end = __ldg(&g_offset[n + 1]);
    float4 acc = make_float4(0.f, 0.f, 0.f, 0.f);

    int j = beg;
    for (; j + 8 <= end; j += 8) {
        int2   se[8];
        uint2  hh[8];
        float2 a01[8], a23[8], a45[8];
#pragma unroll
        for (int u = 0; u < 8; u++) se[u] = __ldg(&g_se[j + u]);
#pragma unroll
        for (int u = 0; u < 8; u++)
            hh[u] = __ldg((const uint2*)(ybase + se[u].x));
#pragma unroll
        for (int u = 0; u < 8; u++) {
            const float2* ea = (const float2*)(eabase + se[u].y);
            a01[u] = __ldg(ea + 0);
            a23[u] = __ldg(ea + 1);
            a45[u] = __ldg(ea + 2);
        }
#pragma unroll
        for (int u = 0; u < 8; u++)
            edge_accum(acc, hh[u], a01[u], a23[u], a45[u], w2);
    }
    if (j + 4 <= end) {
        int2   se[4];
        uint2  hh[4];
        float2 a01[4], a23[4], a45[4];
#pragma unroll
        for (int u = 0; u < 4; u++) se[u] = __ldg(&g_se[j + u]);
#pragma unroll
        for (int u = 0; u < 4; u++)
            hh[u] = __ldg((const uint2*)(ybase + se[u].x));
#pragma unroll
        for (int u = 0; u < 4; u++) {
            const float2* ea = (const float2*)(eabase + se[u].y);
            a01[u] = __ldg(ea + 0);
            a23[u] = __ldg(ea + 1);
            a45[u] = __ldg(ea + 2);
        }
#pragma unroll
        for (int u = 0; u < 4; u++)
            edge_accum(acc, hh[u], a01[u], a23[u], a45[u], w2);
        j += 4;
    }
    for (; j < end; j++) {
        int2 se = __ldg(&g_se[j]);
        uint2 hh = __ldg((const uint2*)(ybase + se.x));
        const float2* ea = (const float2*)(eabase + se.y);
        float2 a01 = __ldg(ea + 0);
        float2 a23 = __ldg(ea + 1);
        float2 a45 = __ldg(ea + 2);
        edge_accum(acc, hh, a01, a23, a45, w2);
    }

    const float degf = (float)(end - beg);
    float4* o = (float4*)(out + (size_t)n * 128) + lane;
    float4 cur = *o;
    cur.x += acc.x - degf;
    cur.y += acc.y - degf;
    cur.z += acc.z - degf;
    cur.w += acc.w - degf;
    *o = cur;
}

// ---------------------------------------------------------------------------
extern "C" void kernel_launch(void* const* d_in, const int* in_sizes, int n_in,
                              void* d_out, int out_size)
{
    const float* x      = (const float*)d_in[0];
    const void*  ei     = d_in[1];
    const float* eattr  = (const float*)d_in[2];
    const float* gs     = (const float*)d_in[3];
    const float* W_neg  = (const float*)d_in[4];
    const float* b_neg  = (const float*)d_in[5];
    const float* W_root = (const float*)d_in[6];
    const float* b_root = (const float*)d_in[7];
    float* out = (float*)d_out;

    const int N  = in_sizes[0] / 128;   // 100000
    const int E  = in_sizes[2] / 6;     // 1600000
    const int NB = (N + 255) / 256;

    // Fork a side stream for the CSR build so it overlaps the node GEMM.
    // Created per call (kernel_launch runs only a handful of times; streams
    // intentionally not destroyed to stay capture-safe). Falls back to the
    // single-stream path if anything fails.
    cudaStream_t s1 = 0;
    cudaEvent_t ev0 = 0, ev1 = 0;
    bool forked = false;
    if (cudaStreamCreateWithFlags(&s1, cudaStreamNonBlocking) == cudaSuccess) {
        if (cudaEventCreateWithFlags(&ev0, cudaEventDisableTiming) == cudaSuccess &&
            cudaEventCreateWithFlags(&ev1, cudaEventDisableTiming) == cudaSuccess) {
            forked = (cudaEventRecord(ev0, 0) == cudaSuccess) &&
                     (cudaStreamWaitEvent(s1, ev0, 0) == cudaSuccess);
        }
        if (!forked) s1 = 0;
    } else {
        s1 = 0;
    }

    prep_kernel<<<128, 256, 0, s1>>>((const int*)ei, in_sizes[1], N);
    hist_kernel<<<(E + 255) / 256, 256, 0, s1>>>(ei, E);
    scan1_kernel<<<NB, 256, 0, s1>>>(N);
    scan2_kernel<<<1, 1024, 0, s1>>>(NB);
    scan3_kernel<<<NB, 256, 0, s1>>>(N, E);
    scatter_kernel<<<(E + 255) / 256, 256, 0, s1>>>(ei, E);

    node_gemm_kernel<<<(N + 63) / 64, 256>>>(x, gs, W_neg, b_neg,
                                             W_root, b_root, out, N);

    if (forked) {
        cudaEventRecord(ev1, s1);
        cudaStreamWaitEvent(0, ev1, 0);
    }

    gather_kernel<<<(N * 32 + 255) / 256, 256>>>(W_neg, eattr, out, N);
}

// round 14
// speedup vs baseline: 1.7526x; 1.0736x over previous
#include <cuda_runtime.h>
#include <cuda_fp16.h>
#include <math.h>

// NodeConv:
//   xs = [x | gs]  (133)
//   y_neg[n]  = xs[n] @ W_neg[0:133] + b_neg           (per NODE, stored fp16)
//   out[n]    = elu(xs[n] @ W_root + b_root)
//   out[dst] += sum_{e: dst(e)=dst} elu(y_neg[src(e)] + ea[e] @ W_neg[133:139])
//
// R13 winner + fat 16B CSR records: scatter packs {src*256, ea[6] as fp16}
// so gather has ONE random load per edge (y_neg row); the record stream is
// sequential. Scatter's extra cost rides the forked stream, hidden behind
// the node GEMM.

#define NMAX 100000
#define EMAX 1600000
#define NBMAX ((NMAX + 255) / 256)

__device__ __half g_yneg[(size_t)NMAX * 128];
__device__ uint4  g_rec[EMAX];   // sorted-by-dst: {src*256, ea01h, ea23h, ea45h}
__device__ int    g_count[NMAX];
__device__ int    g_offset[NMAX + 1];
__device__ int    g_cursor[NMAX];
__device__ int    g_blocksum[NBMAX];
__device__ int    g_blockoff[NBMAX];
__device__ int    g_is64;

// Branchless ELU: exact for v>=0 (__expf(0)==1), ~1e-7 abs err for v<0.
__device__ __forceinline__ float eluf(float v) {
    float neg = fminf(v, 0.0f);
    float pos = fmaxf(v, 0.0f);
    return pos + (__expf(neg) - 1.0f);
}

__device__ __forceinline__ int load_idx(const void* ei, int is64, size_t pos) {
    return is64 ? (int)__ldg((const long long*)ei + pos)
                : __ldg((const int*)ei + pos);
}

// ---------------------------------------------------------------------------
__global__ void prep_kernel(const int* __restrict__ ei32, int nwords, int N) {
    if (blockIdx.x == 0) {
        int nz = 0;
        for (int i = 1 + 2 * threadIdx.x; i < min(nwords, 4096); i += 2 * blockDim.x)
            nz |= (ei32[i] != 0);
        int any = __syncthreads_or(nz);
        if (threadIdx.x == 0) g_is64 = any ? 0 : 1;
    }
    for (int i = blockIdx.x * blockDim.x + threadIdx.x; i < N;
         i += gridDim.x * blockDim.x)
        g_count[i] = 0;
}

// ---------------------------------------------------------------------------
__global__ void hist_kernel(const void* __restrict__ ei, int E) {
    const int is64 = g_is64;
    int e = blockIdx.x * blockDim.x + threadIdx.x;
    if (e < E) atomicAdd(&g_count[load_idx(ei, is64, e)], 1);
}

// ---------------------------------------------------------------------------
__global__ __launch_bounds__(256)
void scan1_kernel(int N) {
    const int tid = threadIdx.x, lane = tid & 31, w = tid >> 5;
    __shared__ int wsum[8];
    int i = blockIdx.x * 256 + tid;
    int v = (i < N) ? g_count[i] : 0;
#pragma unroll
    for (int o = 16; o > 0; o >>= 1) v += __shfl_down_sync(0xffffffffu, v, o);
    if (lane == 0) wsum[w] = v;
    __syncthreads();
    if (tid == 0) {
        int s = 0;
#pragma unroll
        for (int k = 0; k < 8; k++) s += wsum[k];
        g_blocksum[blockIdx.x] = s;
    }
}

__global__ __launch_bounds__(1024)
void scan2_kernel(int NB) {
    const int tid = threadIdx.x, lane = tid & 31, w = tid >> 5;
    __shared__ int wtot[32];
    int c = (tid < NB) ? g_blocksum[tid] : 0;
    int v = c;
#pragma unroll
    for (int o = 1; o < 32; o <<= 1) {
        int t = __shfl_up_sync(0xffffffffu, v, o);
        if (lane >= o) v += t;
    }
    if (lane == 31) wtot[w] = v;
    __syncthreads();
    if (w == 0) {
        int s = wtot[lane];
#pragma unroll
        for (int o = 1; o < 32; o <<= 1) {
            int t = __shfl_up_sync(0xffffffffu, s, o);
            if (lane >= o) s += t;
        }
        wtot[lane] = s;
    }
    __syncthreads();
    int excl = ((w == 0) ? 0 : wtot[w - 1]) + v - c;
    if (tid < NB) g_blockoff[tid] = excl;
}

__global__ __launch_bounds__(256)
void scan3_kernel(int N, int E) {
    const int tid = threadIdx.x, lane = tid & 31, w = tid >> 5;
    __shared__ int wtot[8];
    int i = blockIdx.x * 256 + tid;
    int c = (i < N) ? g_count[i] : 0;
    int v = c;
#pragma unroll
    for (int o = 1; o < 32; o <<= 1) {
        int t = __shfl_up_sync(0xffffffffu, v, o);
        if (lane >= o) v += t;
    }
    if (lane == 31) wtot[w] = v;
    __syncthreads();
    if (w == 0 && lane < 8) {
        int s = wtot[lane];
#pragma unroll
        for (int o = 1; o < 8; o <<= 1) {
            int t = __shfl_up_sync(0x000000ffu, s, o);
            if (lane >= o) s += t;
        }
        wtot[lane] = s;
    }
    __syncthreads();
    int excl = g_blockoff[blockIdx.x] + ((w == 0) ? 0 : wtot[w - 1]) + v - c;
    if (i < N) {
        g_offset[i] = excl;
        g_cursor[i] = excl;
    }
    if (i == 0) g_offset[N] = E;
}

// ---------------------------------------------------------------------------
// Scatter: pack {src*256, ea[6]->fp16} into a 16B record in the dst bucket.
// ea read is fully coalesced (sequential e); the 16B store is random.
// Runs on the forked stream, hidden behind the node GEMM.
// ---------------------------------------------------------------------------
__global__ __launch_bounds__(256)
void scatter_kernel(const void* __restrict__ ei,
                    const float* __restrict__ edge_attr, int E) {
    const int is64 = g_is64;
    int e = blockIdx.x * blockDim.x + threadIdx.x;
    if (e >= E) return;
    int dst = load_idx(ei, is64, e);
    int src = load_idx(ei, is64, (size_t)E + e);
    const float2* ea = (const float2*)(edge_attr + (size_t)e * 6);
    float2 p0 = __ldg(ea + 0);
    float2 p1 = __ldg(ea + 1);
    float2 p2 = __ldg(ea + 2);
    __half2 h01 = __float22half2_rn(p0);
    __half2 h23 = __float22half2_rn(p1);
    __half2 h45 = __float22half2_rn(p2);
    uint4 rec;
    rec.x = (unsigned)(src * 256);
    rec.y = *(unsigned*)&h01;
    rec.z = *(unsigned*)&h23;
    rec.w = *(unsigned*)&h45;
    int pos = atomicAdd(&g_cursor[dst], 1);
    g_rec[pos] = rec;
}

// ---------------------------------------------------------------------------
// K1: fused node GEMM on fma.rn.f32x2 (R8/R9 winner, unchanged).
// Tile = 64 nodes x 256 outputs (128 y_neg fp16 | 128 root fp32).
// ---------------------------------------------------------------------------
__global__ __launch_bounds__(256, 2)
void node_gemm_kernel(const float* __restrict__ x,
                      const float* __restrict__ gs,
                      const float* __restrict__ W_neg,   // [139][128]
                      const float* __restrict__ b_neg,
                      const float* __restrict__ W_root,  // [133][128]
                      const float* __restrict__ b_root,
                      float* __restrict__ out,
                      int N)
{
    __shared__ __align__(16) float As[133][68];   // transposed, 16B-aligned rows
    const int tid = threadIdx.x;
    const int n0 = blockIdx.x * 64;

    for (int i = tid; i < 64 * 133; i += 256) {
        int m = i / 133;
        int k = i - m * 133;
        int n = n0 + m;
        float v = 0.0f;
        if (n < N) v = (k < 128) ? x[(size_t)n * 128 + k]
                                 : gs[(size_t)n * 5 + (k - 128)];
        As[k][m] = v;
    }
    __syncthreads();

    const int c = tid & 31;
    const int r = tid >> 5;
    const bool isRoot = (c >= 16);
    const float* Wsel = isRoot ? W_root : W_neg;
    const float* bsel = isRoot ? b_root : b_neg;
    const int cb = (isRoot ? (c - 16) : c) * 8;

    unsigned long long acc[4][8];
#pragma unroll
    for (int j = 0; j < 8; j++) {
        float bv = __ldg(bsel + cb + j);
        unsigned long long bb;
        asm("mov.b64 %0, {%1, %1};" : "=l"(bb) : "f"(bv));
#pragma unroll
        for (int p = 0; p < 4; p++) acc[p][j] = bb;
    }

#pragma unroll 2
    for (int k = 0; k < 133; k++) {
        float4 b0 = __ldg((const float4*)(Wsel + (size_t)k * 128 + cb));
        float4 b1 = __ldg((const float4*)(Wsel + (size_t)k * 128 + cb + 4));
        float4 a0 = *(const float4*)&As[k][r * 8];
        float4 a1 = *(const float4*)&As[k][r * 8 + 4];

        unsigned long long ap[4], wd[8];
        asm("mov.b64 %0, {%1, %2};" : "=l"(ap[0]) : "f"(a0.x), "f"(a0.y));
        asm("mov.b64 %0, {%1, %2};" : "=l"(ap[1]) : "f"(a0.z), "f"(a0.w));
        asm("mov.b64 %0, {%1, %2};" : "=l"(ap[2]) : "f"(a1.x), "f"(a1.y));
        asm("mov.b64 %0, {%1, %2};" : "=l"(ap[3]) : "f"(a1.z), "f"(a1.w));
        asm("mov.b64 %0, {%1, %1};" : "=l"(wd[0]) : "f"(b0.x));
        asm("mov.b64 %0, {%1, %1};" : "=l"(wd[1]) : "f"(b0.y));
        asm("mov.b64 %0, {%1, %1};" : "=l"(wd[2]) : "f"(b0.z));
        asm("mov.b64 %0, {%1, %1};" : "=l"(wd[3]) : "f"(b0.w));
        asm("mov.b64 %0, {%1, %1};" : "=l"(wd[4]) : "f"(b1.x));
        asm("mov.b64 %0, {%1, %1};" : "=l"(wd[5]) : "f"(b1.y));
        asm("mov.b64 %0, {%1, %1};" : "=l"(wd[6]) : "f"(b1.z));
        asm("mov.b64 %0, {%1, %1};" : "=l"(wd[7]) : "f"(b1.w));

#pragma unroll
        for (int p = 0; p < 4; p++)
#pragma unroll
            for (int j = 0; j < 8; j++)
                asm("fma.rn.f32x2 %0, %1, %2, %0;"
                    : "+l"(acc[p][j]) : "l"(ap[p]), "l"(wd[j]));
    }

#pragma unroll
    for (int p = 0; p < 4; p++) {
        float lo[8], hi[8];
#pragma unroll
        for (int j = 0; j < 8; j++)
            asm("mov.b64 {%0, %1}, %2;" : "=f"(lo[j]), "=f"(hi[j]) : "l"(acc[p][j]));

        int n_lo = n0 + r * 8 + 2 * p;
        int n_hi = n_lo + 1;
        if (isRoot) {
            if (n_lo < N) {
                *((float4*)(out + (size_t)n_lo * 128 + cb)) =
                    make_float4(eluf(lo[0]), eluf(lo[1]), eluf(lo[2]), eluf(lo[3]));
                *((float4*)(out + (size_t)n_lo * 128 + cb + 4)) =
                    make_float4(eluf(lo[4]), eluf(lo[5]), eluf(lo[6]), eluf(lo[7]));
            }
            if (n_hi < N) {
                *((float4*)(out + (size_t)n_hi * 128 + cb)) =
                    make_float4(eluf(hi[0]), eluf(hi[1]), eluf(hi[2]), eluf(hi[3]));
                *((float4*)(out + (size_t)n_hi * 128 + cb + 4)) =
                    make_float4(eluf(hi[4]), eluf(hi[5]), eluf(hi[6]), eluf(hi[7]));
            }
        } else {
            if (n_lo < N) {
                uint4 pk;
                __half2 h0 = __float22half2_rn(make_float2(lo[0], lo[1]));
                __half2 h1 = __float22half2_rn(make_float2(lo[2], lo[3]));
                __half2 h2 = __float22half2_rn(make_float2(lo[4], lo[5]));
                __half2 h3 = __float22half2_rn(make_float2(lo[6], lo[7]));
                pk.x = *(unsigned*)&h0; pk.y = *(unsigned*)&h1;
                pk.z = *(unsigned*)&h2; pk.w = *(unsigned*)&h3;
                *((uint4*)(g_yneg + (size_t)n_lo * 128 + cb)) = pk;
            }
            if (n_hi < N) {
                uint4 pk;
                __half2 h0 = __float22half2_rn(make_float2(hi[0], hi[1]));
                __half2 h1 = __float22half2_rn(make_float2(hi[2], hi[3]));
                __half2 h2 = __float22half2_rn(make_float2(hi[4], hi[5]));
                __half2 h3 = __float22half2_rn(make_float2(hi[6], hi[7]));
                pk.x = *(unsigned*)&h0; pk.y = *(unsigned*)&h1;
                pk.z = *(unsigned*)&h2; pk.w = *(unsigned*)&h3;
                *((uint4*)(g_yneg + (size_t)n_hi * 128 + cb)) = pk;
            }
        }
    }
}

// ---------------------------------------------------------------------------
// Per-edge gather body: W2 FMA (fp32, ea from fp16), then accumulate
// max(v,0)+exp(min(v,0)); the "-1" is applied once per node as -degree.
// ---------------------------------------------------------------------------
__device__ __forceinline__ void edge_accum(float4& acc, uint2 hh,
                                           float2 a01, float2 a23, float2 a45,
                                           const float4* w2) {
    float2 f01 = __half22float2(*(__half2*)&hh.x);
    float2 f23 = __half22float2(*(__half2*)&hh.y);
    float4 v = make_float4(f01.x, f01.y, f23.x, f23.y);
    v.x += a01.x * w2[0].x + a01.y * w2[1].x + a23.x * w2[2].x
         + a23.y * w2[3].x + a45.x * w2[4].x + a45.y * w2[5].x;
    v.y += a01.x * w2[0].y + a01.y * w2[1].y + a23.x * w2[2].y
         + a23.y * w2[3].y + a45.x * w2[4].y + a45.y * w2[5].y;
    v.z += a01.x * w2[0].z + a01.y * w2[1].z + a23.x * w2[2].z
         + a23.y * w2[3].z + a45.x * w2[4].z + a45.y * w2[5].z;
    v.w += a01.x * w2[0].w + a01.y * w2[1].w + a23.x * w2[2].w
         + a23.y * w2[3].w + a45.x * w2[4].w + a45.y * w2[5].w;
    acc.x += fmaxf(v.x, 0.0f); acc.x += __expf(fminf(v.x, 0.0f));
    acc.y += fmaxf(v.y, 0.0f); acc.y += __expf(fminf(v.y, 0.0f));
    acc.z += fmaxf(v.z, 0.0f); acc.z += __expf(fminf(v.z, 0.0f));
    acc.w += fmaxf(v.w, 0.0f); acc.w += __expf(fminf(v.w, 0.0f));
}

// ---------------------------------------------------------------------------
// Gather: one warp per node, unroll 8/4/1. Per edge: one sequential 16B
// record load + one random y_neg row load. No edge_attr access.
// ---------------------------------------------------------------------------
__global__ __launch_bounds__(256)
void gather_kernel(const float* __restrict__ W_neg,      // [139][128]
                   float* __restrict__ out, int N)
{
    const int lane = threadIdx.x & 31;
    const int warp = blockIdx.x * (blockDim.x >> 5) + (threadIdx.x >> 5);
    if (warp >= N) return;
    const int n = warp;

    float4 w2[6];
#pragma unroll
    for (int d = 0; d < 6; d++)
        w2[d] = __ldg((const float4*)(W_neg + (size_t)(133 + d) * 128) + lane);

    const char* ybase = (const char*)g_yneg + lane * 8;

    const int beg = __ldg(&g_offset[n]);
    const int end = __ldg(&g_offset[n + 1]);
    float4 acc = make_float4(0.f, 0.f, 0.f, 0.f);

    int j = beg;
    for (; j + 8 <= end; j += 8) {
        uint4 rc[8];
        uint2 hh[8];
#pragma unroll
        for (int u = 0; u < 8; u++) rc[u] = __ldg(&g_rec[j + u]);
#pragma unroll
        for (int u = 0; u < 8; u++)
            hh[u] = __ldg((const uint2*)(ybase + rc[u].x));
#pragma unroll
        for (int u = 0; u < 8; u++) {
            float2 a01 = __half22float2(*(__half2*)&rc[u].y);
            float2 a23 = __half22float2(*(__half2*)&rc[u].z);
            float2 a45 = __half22float2(*(__half2*)&rc[u].w);
            edge_accum(acc, hh[u], a01, a23, a45, w2);
        }
    }
    if (j + 4 <= end) {
        uint4 rc[4];
        uint2 hh[4];
#pragma unroll
        for (int u = 0; u < 4; u++) rc[u] = __ldg(&g_rec[j + u]);
#pragma unroll
        for (int u = 0; u < 4; u++)
            hh[u] = __ldg((const uint2*)(ybase + rc[u].x));
#pragma unroll
        for (int u = 0; u < 4; u++) {
            float2 a01 = __half22float2(*(__half2*)&rc[u].y);
            float2 a23 = __half22float2(*(__half2*)&rc[u].z);
            float2 a45 = __half22float2(*(__half2*)&rc[u].w);
            edge_accum(acc, hh[u], a01, a23, a45, w2);
        }
        j += 4;
    }
    for (; j < end; j++) {
        uint4 rc = __ldg(&g_rec[j]);
        uint2 hh = __ldg((const uint2*)(ybase + rc.x));
        float2 a01 = __half22float2(*(__half2*)&rc.y);
        float2 a23 = __half22float2(*(__half2*)&rc.z);
        float2 a45 = __half22float2(*(__half2*)&rc.w);
        edge_accum(acc, hh, a01, a23, a45, w2);
    }

    const float degf = (float)(end - beg);
    float4* o = (float4*)(out + (size_t)n * 128) + lane;
    float4 cur = *o;
    cur.x += acc.x - degf;
    cur.y += acc.y - degf;
    cur.z += acc.z - degf;
    cur.w += acc.w - degf;
    *o = cur;
}

// ---------------------------------------------------------------------------
extern "C" void kernel_launch(void* const* d_in, const int* in_sizes, int n_in,
                              void* d_out, int out_size)
{
    const float* x      = (const float*)d_in[0];
    const void*  ei     = d_in[1];
    const float* eattr  = (const float*)d_in[2];
    const float* gs     = (const float*)d_in[3];
    const float* W_neg  = (const float*)d_in[4];
    const float* b_neg  = (const float*)d_in[5];
    const float* W_root = (const float*)d_in[6];
    const float* b_root = (const float*)d_in[7];
    float* out = (float*)d_out;

    const int N  = in_sizes[0] / 128;   // 100000
    const int E  = in_sizes[2] / 6;     // 1600000
    const int NB = (N + 255) / 256;

    // Fork a side stream for the CSR build so it overlaps the node GEMM.
    cudaStream_t s1 = 0;
    cudaEvent_t ev0 = 0, ev1 = 0;
    bool forked = false;
    if (cudaStreamCreateWithFlags(&s1, cudaStreamNonBlocking) == cudaSuccess) {
        if (cudaEventCreateWithFlags(&ev0, cudaEventDisableTiming) == cudaSuccess &&
            cudaEventCreateWithFlags(&ev1, cudaEventDisableTiming) == cudaSuccess) {
            forked = (cudaEventRecord(ev0, 0) == cudaSuccess) &&
                     (cudaStreamWaitEvent(s1, ev0, 0) == cudaSuccess);
        }
        if (!forked) s1 = 0;
    } else {
        s1 = 0;
    }

    prep_kernel<<<128, 256, 0, s1>>>((const int*)ei, in_sizes[1], N);
    hist_kernel<<<(E + 255) / 256, 256, 0, s1>>>(ei, E);
    scan1_kernel<<<NB, 256, 0, s1>>>(N);
    scan2_kernel<<<1, 1024, 0, s1>>>(NB);
    scan3_kernel<<<NB, 256, 0, s1>>>(N, E);
    scatter_kernel<<<(E + 255) / 256, 256, 0, s1>>>(ei, eattr, E);

    node_gemm_kernel<<<(N + 63) / 64, 256>>>(x, gs, W_neg, b_neg,
                                             W_root, b_root, out, N);

    if (forked) {
        cudaEventRecord(ev1, s1);
        cudaStreamWaitEvent(0, ev1, 0);
    }

    gather_kernel<<<(N * 32 + 255) / 256, 256>>>(W_neg, out, N);
}